// round 9
// baseline (speedup 1.0000x reference)
#include <cuda_runtime.h>
#include <cstdint>

// ---------------------------------------------------------------------------
// QuantumRNNCell fused persistent kernel, v9 (warp-specialized + TMA bulk):
//   out[b,h] = hx[b,h] + sum_j q[b,j] * fc_w[h,j] + fc_b[h]
// Block = 384 threads, 3 CTAs/SM:
//   warps 0..3  : sim warps (packed 2-rows-per-warp 6-qubit sim, analytic
//                 product-state encoding). Iter it: sim tile t+stride -> sq[(it+1)&1].
//   warps 4..11 : stream warps (256 thr, fixed column group, fc weights in regs).
//                 One elected thread issues a single 32KB cp.async.bulk per tile
//                 (hx tiles are contiguous) completed via mbarrier; all stream
//                 threads wait the stage mbarrier, then FMA+store tile t.
// ONE __syncthreads per tile; next tile's bulk copy is in flight during FMA.
// ---------------------------------------------------------------------------

#define NQ 6
#define NLAYERS 3
#define HDIM 1024
#define TR 8
#define TILE_F4 (TR * 256)           // 2048 float4 = 32 KB
#define TILE_BYTES (TILE_F4 * 16)
#define NSIMW 4
#define NTHREADS 384

// ---- mbarrier / bulk-copy PTX ----------------------------------------------
#define MBAR_INIT(addr, cnt) \
    asm volatile("mbarrier.init.shared.b64 [%0], %1;" :: "r"(addr), "r"(cnt) : "memory")
#define MBAR_EXPECT_TX(addr, bytes) \
    asm volatile("mbarrier.arrive.expect_tx.shared.b64 _, [%0], %1;" \
                 :: "r"(addr), "r"(bytes) : "memory")
#define MBAR_WAIT(addr, parity) do {                                          \
    asm volatile(                                                             \
        "{\n\t.reg .pred P;\n\t"                                              \
        "WAIT_%=:\n\t"                                                        \
        "mbarrier.try_wait.parity.acquire.cta.shared::cta.b64 P, [%0], %1, 0x989680;\n\t" \
        "@P bra.uni DONE_%=;\n\t"                                             \
        "bra.uni WAIT_%=;\n\t"                                                \
        "DONE_%=:\n\t}"                                                       \
        :: "r"(addr), "r"(parity) : "memory");                                \
} while (0)

__device__ __forceinline__ void bulk_copy(uint32_t dst_smem, const void* gsrc,
                                          uint32_t bytes, uint32_t mbar) {
    asm volatile(
        "cp.async.bulk.shared::cta.global.mbarrier::complete_tx::bytes "
        "[%0], [%1], %2, [%3];"
        :: "r"(dst_smem), "l"(gsrc), "r"(bytes), "r"(mbar) : "memory");
}

// ---- packed (2-row) gate helpers (validated R4/R7/R8) ----------------------
// a[8] = {re,im} x hi2(0..3); hi2 bit1 = state bit5, hi2 bit0 = state bit4.
// State bits 3..0 = lane16 bits 3..0.
__device__ __forceinline__ void ry_pair(float a[8], int i0, int i1, float c, float s) {
    float re0 = a[2*i0], im0 = a[2*i0+1], re1 = a[2*i1], im1 = a[2*i1+1];
    a[2*i0]   = c*re0 - s*re1;
    a[2*i0+1] = c*im0 - s*im1;
    a[2*i1]   = s*re0 + c*re1;
    a[2*i1+1] = s*im0 + c*im1;
}
__device__ __forceinline__ void ry_shfl(float a[8], int m, float c, float s, unsigned lane) {
    float sg = (lane & (unsigned)m) ? s : -s;
#pragma unroll
    for (int k = 0; k < 4; k++) {
        float orr = __shfl_xor_sync(0xFFFFFFFFu, a[2*k],   m);
        float oii = __shfl_xor_sync(0xFFFFFFFFu, a[2*k+1], m);
        a[2*k]   = c*a[2*k]   + sg*orr;
        a[2*k+1] = c*a[2*k+1] + sg*oii;
    }
}
__device__ __forceinline__ void apply_ry(int w, float a[8], float c, float s, unsigned lane) {
    if (w == 0)      { ry_pair(a, 0, 2, c, s); ry_pair(a, 1, 3, c, s); }
    else if (w == 1) { ry_pair(a, 0, 1, c, s); ry_pair(a, 2, 3, c, s); }
    else             ry_shfl(a, 1 << (5 - w), c, s, lane);
}

__device__ __forceinline__ void apply_cnot_ring(int q, float a[8], unsigned lane) {
    if (q == 0) {
        float t;
        t = a[4]; a[4] = a[6]; a[6] = t;
        t = a[5]; a[5] = a[7]; a[7] = t;
    } else if (q == 1) {
#pragma unroll
        for (int k = 1; k < 4; k += 2) {
            a[2*k]   = __shfl_xor_sync(0xFFFFFFFFu, a[2*k],   8);
            a[2*k+1] = __shfl_xor_sync(0xFFFFFFFFu, a[2*k+1], 8);
        }
    } else if (q == 5) {
        if (lane & 1u) {
            float t;
            t = a[0]; a[0] = a[4]; a[4] = t;
            t = a[1]; a[1] = a[5]; a[5] = t;
            t = a[2]; a[2] = a[6]; a[6] = t;
            t = a[3]; a[3] = a[7]; a[7] = t;
        }
    } else {
        int cb = 1 << (5 - q);
        int tm = 1 << (4 - q);
        bool ctrl = (lane & (unsigned)cb) != 0;
#pragma unroll
        for (int k = 0; k < 4; k++) {
            float vr = __shfl_xor_sync(0xFFFFFFFFu, a[2*k],   tm);
            float vi = __shfl_xor_sync(0xFFFFFFFFu, a[2*k+1], tm);
            if (ctrl) { a[2*k] = vr; a[2*k+1] = vi; }
        }
    }
}

// ---- full sim for one row (half-warp) --------------------------------------
__device__ __forceinline__ void sim_rows(
    const float* __restrict__ x, const float* swc, const float* sws,
    float* sqdst, int trow, int b, unsigned lane, unsigned lane16) {
    float cx[NQ], sx[NQ];
#pragma unroll
    for (int j = 0; j < NQ; j++) {
        __sincosf(__ldg(&x[b * NQ + j]) * 0.5f, &sx[j], &cx[j]);
    }

    float v0r[NQ], v0i[NQ], v1r[NQ], v1i[NQ];
#pragma unroll
    for (int iw = 0; iw < NQ; iw++) {
        int j1 = (iw + 1 > 5) ? iw - 5 : iw + 1;
        int j2 = (iw + 2 > 5) ? iw - 4 : iw + 2;
        float ar = cx[j1] * cx[iw];
        float ai = sx[j1] * sx[iw];
        float br = sx[j1] * cx[iw];
        float bi = -cx[j1] * sx[iw];
        float cz = cx[j2], sz = sx[j2];
        v0r[iw] = ar * cz + ai * sz;
        v0i[iw] = ai * cz - ar * sz;
        v1r[iw] = br * cz - bi * sz;
        v1i[iw] = bi * cz + br * sz;
    }

    float fr, fi;
    {
        bool bs = (lane16 & 8u) != 0;
        fr = bs ? v1r[2] : v0r[2];
        fi = bs ? v1i[2] : v0i[2];
    }
#pragma unroll
    for (int w2 = 3; w2 <= 5; w2++) {
        bool bs = (lane16 & (1u << (5 - w2))) != 0;
        float tr = bs ? v1r[w2] : v0r[w2];
        float ti = bs ? v1i[w2] : v0i[w2];
        float nr = fr * tr - fi * ti;
        float ni = fr * ti + fi * tr;
        fr = nr; fi = ni;
    }

    float a[8];
#pragma unroll
    for (int k = 0; k < 4; k++) {
        float u0r = (k & 2) ? v1r[0] : v0r[0];
        float u0i = (k & 2) ? v1i[0] : v0i[0];
        float u1r = (k & 1) ? v1r[1] : v0r[1];
        float u1i = (k & 1) ? v1i[1] : v0i[1];
        float gr = u0r * u1r - u0i * u1i;
        float gi = u0r * u1i + u0i * u1r;
        a[2*k]   = gr * fr - gi * fi;
        a[2*k+1] = gr * fi + gi * fr;
    }

#pragma unroll
    for (int l = 0; l < NLAYERS; l++) {
#pragma unroll
        for (int q = 0; q < NQ; q++)
            apply_ry(q, a, swc[l * NQ + q], sws[l * NQ + q], lane);
#pragma unroll
        for (int q = 0; q < NQ; q++) apply_cnot_ring(q, a, lane);
    }

    float p0 = a[0]*a[0] + a[1]*a[1];
    float p1 = a[2]*a[2] + a[3]*a[3];
    float p2 = a[4]*a[4] + a[5]*a[5];
    float p3 = a[6]*a[6] + a[7]*a[7];
    float ptot = p0 + p1 + p2 + p3;

    float e[NQ];
    e[0] = (p0 + p1) - (p2 + p3);
    e[1] = (p0 - p1) + (p2 - p3);
#pragma unroll
    for (int j = 2; j < NQ; j++) {
        float sg = (lane16 & (unsigned)(1 << (5 - j))) ? -1.0f : 1.0f;
        e[j] = sg * ptot;
    }
#pragma unroll
    for (int off = 8; off; off >>= 1) {
#pragma unroll
        for (int j = 0; j < NQ; j++)
            e[j] += __shfl_xor_sync(0xFFFFFFFFu, e[j], off);
    }
    if (lane16 == 0) {
#pragma unroll
        for (int j = 0; j < NQ; j++) sqdst[trow * 8 + j] = e[j];
        sqdst[trow * 8 + 6] = 0.0f;
        sqdst[trow * 8 + 7] = 0.0f;
    }
}

// ---- fused persistent kernel ------------------------------------------------
__global__ __launch_bounds__(NTHREADS, 3)
void fused_kernel(const float* __restrict__ x,
                  const float* __restrict__ hx,
                  const float* __restrict__ qw,    // (3,6)
                  const float* __restrict__ fc_w,  // (1024,6)
                  const float* __restrict__ fc_b,  // (1024,)
                  float* __restrict__ out,
                  int B, int ntiles) {
    extern __shared__ unsigned char smem_raw[];
    float4* sbuf = (float4*)smem_raw;                      // 2 * TILE_F4 (64KB)
    float*  sq   = (float*)(sbuf + 2 * TILE_F4);           // 2 * TR * 8
    float*  swc  = sq + 2 * TR * 8;                        // 18
    float*  sws  = swc + NLAYERS * NQ;                     // 18
    // mbarriers: 8-byte aligned right after (pad to 8)
    uint64_t* mbar64 = (uint64_t*)(((uintptr_t)(sws + NLAYERS * NQ) + 7) & ~(uintptr_t)7);

    const int tid = threadIdx.x;
    const int warp = tid >> 5;
    const unsigned lane = tid & 31u;
    const unsigned lane16 = lane & 15u;
    const int half = (int)(lane >> 4);
    const int stride = gridDim.x;
    const bool is_stream = (warp >= NSIMW);
    const int st = tid - NSIMW * 32;       // stream thread id 0..255

    const uint32_t mbar0 = (uint32_t)__cvta_generic_to_shared(&mbar64[0]);
    const uint32_t mbar1 = (uint32_t)__cvta_generic_to_shared(&mbar64[1]);
    const uint32_t stage0 = (uint32_t)__cvta_generic_to_shared(&sbuf[0]);
    const uint32_t stage1 = (uint32_t)__cvta_generic_to_shared(&sbuf[TILE_F4]);

    // ---- stream threads: fc weights + bias into registers ----
    float4 w0, w1, w2, w3, w4, w5, bv;
    if (is_stream) {
        const int h0 = 4 * st;
        w0 = make_float4(__ldg(&fc_w[(h0+0)*NQ+0]), __ldg(&fc_w[(h0+1)*NQ+0]),
                         __ldg(&fc_w[(h0+2)*NQ+0]), __ldg(&fc_w[(h0+3)*NQ+0]));
        w1 = make_float4(__ldg(&fc_w[(h0+0)*NQ+1]), __ldg(&fc_w[(h0+1)*NQ+1]),
                         __ldg(&fc_w[(h0+2)*NQ+1]), __ldg(&fc_w[(h0+3)*NQ+1]));
        w2 = make_float4(__ldg(&fc_w[(h0+0)*NQ+2]), __ldg(&fc_w[(h0+1)*NQ+2]),
                         __ldg(&fc_w[(h0+2)*NQ+2]), __ldg(&fc_w[(h0+3)*NQ+2]));
        w3 = make_float4(__ldg(&fc_w[(h0+0)*NQ+3]), __ldg(&fc_w[(h0+1)*NQ+3]),
                         __ldg(&fc_w[(h0+2)*NQ+3]), __ldg(&fc_w[(h0+3)*NQ+3]));
        w4 = make_float4(__ldg(&fc_w[(h0+0)*NQ+4]), __ldg(&fc_w[(h0+1)*NQ+4]),
                         __ldg(&fc_w[(h0+2)*NQ+4]), __ldg(&fc_w[(h0+3)*NQ+4]));
        w5 = make_float4(__ldg(&fc_w[(h0+0)*NQ+5]), __ldg(&fc_w[(h0+1)*NQ+5]),
                         __ldg(&fc_w[(h0+2)*NQ+5]), __ldg(&fc_w[(h0+3)*NQ+5]));
        bv = make_float4(__ldg(&fc_b[h0]), __ldg(&fc_b[h0+1]),
                         __ldg(&fc_b[h0+2]), __ldg(&fc_b[h0+3]));
    }
    if (tid < NLAYERS * NQ) {
        float s, c;
        __sincosf(__ldg(&qw[tid]) * 0.5f, &s, &c);
        swc[tid] = c; sws[tid] = s;
    }
    if (tid == 0) {
        MBAR_INIT(mbar0, 1);
        MBAR_INIT(mbar1, 1);
    }
    __syncthreads();

    const int t0 = blockIdx.x;
    const char* hxb = (const char*)hx;

    // tile byte count (tail-safe)
    auto tile_bytes = [&](int t) -> uint32_t {
        int rows = B - t * TR;
        if (rows > TR) rows = TR;
        return (uint32_t)rows * (HDIM * 4);
    };

    // ---- prologue: bulk-load tile t0 into stage 0; sim tile t0 -> sq[0] ----
    if (tid == NSIMW * 32) {
        uint32_t nb = tile_bytes(t0);
        MBAR_EXPECT_TX(mbar0, nb);
        bulk_copy(stage0, hxb + (size_t)t0 * TILE_BYTES, nb, mbar0);
    }
    if (!is_stream) {
        const int trow = warp * 2 + half;
        sim_rows(x, swc, sws, sq, trow,
                 min(t0 * TR + trow, B - 1), lane, lane16);
    }
    __syncthreads();

    int it = 0;
    for (int t = t0; t < ntiles; t += stride, it++) {
        const int tn = t + stride;

        if (is_stream) {
            // ---- producer: issue next tile's bulk copy into other stage ----
            if (tn < ntiles && st == 0) {
                uint32_t nb = tile_bytes(tn);
                uint32_t mb = ((it + 1) & 1) ? mbar1 : mbar0;
                uint32_t sg = ((it + 1) & 1) ? stage1 : stage0;
                MBAR_EXPECT_TX(mb, nb);
                bulk_copy(sg, hxb + (size_t)tn * TILE_BYTES, nb, mb);
            }

            // ---- wait tile t's stage, then FMA + store ----
            MBAR_WAIT((it & 1) ? mbar1 : mbar0, (it >> 1) & 1);

            const float4* buf = &sbuf[(it & 1) * TILE_F4];
            const float* sqr = &sq[(it & 1) * (TR * 8)];
            const int row0 = t * TR;
#pragma unroll
            for (int r = 0; r < TR; r++) {
                int b = row0 + r;
                if (b >= B) break;
                float4 qa = *(const float4*)&sqr[r * 8];
                float4 qb = *(const float4*)&sqr[r * 8 + 4];
                float4 v = buf[r * 256 + st];
                float4 acc = bv;
                acc.x += qa.x*w0.x; acc.y += qa.x*w0.y; acc.z += qa.x*w0.z; acc.w += qa.x*w0.w;
                acc.x += qa.y*w1.x; acc.y += qa.y*w1.y; acc.z += qa.y*w1.z; acc.w += qa.y*w1.w;
                acc.x += qa.z*w2.x; acc.y += qa.z*w2.y; acc.z += qa.z*w2.z; acc.w += qa.z*w2.w;
                acc.x += qa.w*w3.x; acc.y += qa.w*w3.y; acc.z += qa.w*w3.z; acc.w += qa.w*w3.w;
                acc.x += qb.x*w4.x; acc.y += qb.x*w4.y; acc.z += qb.x*w4.z; acc.w += qb.x*w4.w;
                acc.x += qb.y*w5.x; acc.y += qb.y*w5.y; acc.z += qb.y*w5.z; acc.w += qb.y*w5.w;
                v.x += acc.x; v.y += acc.y; v.z += acc.z; v.w += acc.w;
                __stcs((float4*)(out + (size_t)b * HDIM) + st, v);
            }
        } else {
            // ---- sim next tile into the other sq buffer ----
            if (tn < ntiles) {
                const int trow = warp * 2 + half;
                sim_rows(x, swc, sws, &sq[((it + 1) & 1) * (TR * 8)], trow,
                         min(tn * TR + trow, B - 1), lane, lane16);
            }
        }
        __syncthreads();    // orders stage/sq reuse before next iteration's fills
    }
}

// ---- launch ----------------------------------------------------------------
extern "C" void kernel_launch(void* const* d_in, const int* in_sizes, int n_in,
                              void* d_out, int out_size) {
    const float* x    = (const float*)d_in[0];   // (B,6)
    const float* hx   = (const float*)d_in[1];   // (B,1024)
    const float* qw   = (const float*)d_in[2];   // (3,6)
    const float* fc_w = (const float*)d_in[3];   // (1024,6)
    const float* fc_b = (const float*)d_in[4];   // (1024,)
    float* out = (float*)d_out;

    int B = in_sizes[0] / NQ;
    int ntiles = (B + TR - 1) / TR;

    const int smem_bytes = 2 * TILE_F4 * 16 + 2 * TR * 8 * 4
                         + 2 * NLAYERS * NQ * 4 + 32;

    cudaFuncSetAttribute(fused_kernel,
                         cudaFuncAttributeMaxDynamicSharedMemorySize,
                         smem_bytes);

    int grid = 148 * 3;
    if (grid > ntiles) grid = ntiles;
    fused_kernel<<<grid, NTHREADS, smem_bytes>>>(x, hx, qw, fc_w, fc_b, out,
                                                 B, ntiles);
}